// round 1
// baseline (speedup 1.0000x reference)
#include <cuda_runtime.h>
#include <cstdint>

#define BB 32
#define KKS 10
#define TT 128
#define LLS 128
#define DD 1024
#define NTAG 32
#define SS (KKS*LLS)    // 1280
#define CHN KKS         // 10 chunks of 128 support rows

typedef unsigned long long ull;

// ---------------- scratch (device globals; no allocation) ----------------
__device__ float  g_test_mean[BB*TT*DD];     // (B,T,D) 16 MB
__device__ int    g_labels[BB*SS];
__device__ float2 g_cmin[BB*TT*CHN];         // per-chunk (minval, idx-as-float)
__device__ int    g_nn[BB*TT];

// ---------------- kernel 1: test_mean = mean_k test_reps ----------------
__global__ void k_mean(const float* __restrict__ x){
    int idx = blockIdx.x*blockDim.x + threadIdx.x;
    const int n4 = BB*TT*DD/4;
    if (idx >= n4) return;
    int b   = idx / (TT*DD/4);
    int rem = idx - b*(TT*DD/4);
    const float4* p = (const float4*)x + (size_t)b*KKS*(TT*DD/4) + rem;
    float4 a = make_float4(0.f,0.f,0.f,0.f);
#pragma unroll
    for (int k=0;k<KKS;k++){
        float4 v = p[(size_t)k*(TT*DD/4)];
        a.x+=v.x; a.y+=v.y; a.z+=v.z; a.w+=v.w;
    }
    const float s = 1.0f/(float)KKS;
    a.x*=s; a.y*=s; a.z*=s; a.w*=s;
    ((float4*)g_test_mean)[idx] = a;
}

// ---------------- kernel 2: labels = argmax(one_hot) ----------------
__global__ void k_labels(const float* __restrict__ tgt){
    int i = blockIdx.x*blockDim.x + threadIdx.x;
    if (i >= BB*SS) return;
    const float* row = tgt + (size_t)i*NTAG;
    float bv = row[0]; int bi = 0;
#pragma unroll
    for (int n=1;n<NTAG;n++){ float v=row[n]; if (v>bv){bv=v;bi=n;} }
    g_labels[i] = bi;
}

// ---------------- kernel 3: prototype sums (scatter by label) ----------------
// grid (B, D/256), 256 threads; smem accumulation, no atomics.
__global__ __launch_bounds__(256) void k_proto(const float* __restrict__ sup,
                                               float* __restrict__ psum){
    __shared__ float sp[NTAG*256];
    __shared__ int   slab[SS];
    int b = blockIdx.x, d0 = blockIdx.y*256, tid = threadIdx.x;
    for (int i=tid;i<NTAG*256;i+=256) sp[i]=0.f;
    for (int i=tid;i<SS;i+=256) slab[i]=g_labels[b*SS+i];
    __syncthreads();
    const float* base = sup + (size_t)b*SS*DD + d0 + tid;
#pragma unroll 4
    for (int s=0;s<SS;s++){
        float v = base[(size_t)s*DD];
        sp[slab[s]*256 + tid] += v;
    }
    __syncthreads();
    for (int i=tid;i<NTAG*256;i+=256){
        int n=i>>8, d=i&255;
        psum[((size_t)b*NTAG+n)*DD + d0 + d] = sp[i];
    }
}

// ---------------- kernel 4: counts + divide (in place on d_out proto) ----------------
__global__ void k_div(float* __restrict__ proto){
    int b = blockIdx.x, n = blockIdx.y, tid = threadIdx.x;
    __shared__ float red[128];
    float c = 0.f;
    for (int s=tid;s<SS;s+=128) c += (g_labels[b*SS+s]==n) ? 1.f : 0.f;
    red[tid]=c; __syncthreads();
    for (int o=64;o;o>>=1){ if (tid<o) red[tid]+=red[tid+o]; __syncthreads(); }
    float denom = red[0] + 1e-4f;
    float* p = proto + ((size_t)b*NTAG+n)*DD;
    for (int i=tid;i<DD;i+=128) p[i] = p[i] / denom;
}

// ---------------- kernel 5: fp32x2 SGEMM + per-chunk argmin ----------------
// grid (10 chunks, 32 batches); 128x128x1024 per block; 256 threads;
// thread (tx,ty) owns rows {ty*4..+3, 64+ty*4..+3} x cols {tx*4..+3, 64+tx*4..+3}.
__global__ __launch_bounds__(256,1) void k_gemm(const float* __restrict__ sup){
    const int ch = blockIdx.x, b = blockIdx.y;
    const int tid = threadIdx.x;
    const int tx = tid & 15, ty = tid >> 4;
    __shared__ float As[2][16][128];
    __shared__ float Bs[2][16][128];
    __shared__ float snorm[128];

    const float* A  = g_test_mean + (size_t)b*TT*DD;
    const float* Bp = sup + ((size_t)b*SS + (size_t)ch*LLS)*DD;

    // loader: 512 float4 slots per tile, 2 per thread
    const int i0 = tid, i1 = tid + 256;
    const int am0 = i0>>2, ak0 = (i0&3)*4;
    const int am1 = i1>>2, ak1 = (i1&3)*4;
    const float* pA0 = A  + (size_t)am0*DD + ak0;
    const float* pA1 = A  + (size_t)am1*DD + ak1;
    const float* pB0 = Bp + (size_t)am0*DD + ak0;
    const float* pB1 = Bp + (size_t)am1*DD + ak1;

    ull acc[8][4];
#pragma unroll
    for (int i=0;i<8;i++)
#pragma unroll
        for (int j=0;j<4;j++) acc[i][j]=0ull;

    float4 ra0 = *(const float4*)pA0;
    float4 ra1 = *(const float4*)pA1;
    float4 rb0 = *(const float4*)pB0;
    float4 rb1 = *(const float4*)pB1;
    As[0][ak0+0][am0]=ra0.x; As[0][ak0+1][am0]=ra0.y; As[0][ak0+2][am0]=ra0.z; As[0][ak0+3][am0]=ra0.w;
    As[0][ak1+0][am1]=ra1.x; As[0][ak1+1][am1]=ra1.y; As[0][ak1+2][am1]=ra1.z; As[0][ak1+3][am1]=ra1.w;
    Bs[0][ak0+0][am0]=rb0.x; Bs[0][ak0+1][am0]=rb0.y; Bs[0][ak0+2][am0]=rb0.z; Bs[0][ak0+3][am0]=rb0.w;
    Bs[0][ak1+0][am1]=rb1.x; Bs[0][ak1+1][am1]=rb1.y; Bs[0][ak1+2][am1]=rb1.z; Bs[0][ak1+3][am1]=rb1.w;
    __syncthreads();

    for (int kt=0; kt<DD/16; kt++){
        const int buf = kt & 1;
        if (kt < DD/16-1){
            const int off = (kt+1)*16;
            ra0 = *(const float4*)(pA0+off); ra1 = *(const float4*)(pA1+off);
            rb0 = *(const float4*)(pB0+off); rb1 = *(const float4*)(pB1+off);
        }
#pragma unroll
        for (int kk=0;kk<16;kk++){
            float4 a0 = *(const float4*)&As[buf][kk][ty*4];
            float4 a1 = *(const float4*)&As[buf][kk][ty*4+64];
            const ull* br = (const ull*)&Bs[buf][kk][0];
            ull b0 = br[tx*2],    b1 = br[tx*2+1];
            ull b2 = br[tx*2+32], b3 = br[tx*2+33];
            float av[8] = {a0.x,a0.y,a0.z,a0.w,a1.x,a1.y,a1.z,a1.w};
#pragma unroll
            for (int i=0;i<8;i++){
                ull aa;
                asm("mov.b64 %0, {%1, %1};" : "=l"(aa) : "f"(av[i]));
                asm("fma.rn.f32x2 %0, %1, %2, %0;" : "+l"(acc[i][0]) : "l"(aa), "l"(b0));
                asm("fma.rn.f32x2 %0, %1, %2, %0;" : "+l"(acc[i][1]) : "l"(aa), "l"(b1));
                asm("fma.rn.f32x2 %0, %1, %2, %0;" : "+l"(acc[i][2]) : "l"(aa), "l"(b2));
                asm("fma.rn.f32x2 %0, %1, %2, %0;" : "+l"(acc[i][3]) : "l"(aa), "l"(b3));
            }
        }
        if (kt < DD/16-1){
            const int nb = buf^1;
            As[nb][ak0+0][am0]=ra0.x; As[nb][ak0+1][am0]=ra0.y; As[nb][ak0+2][am0]=ra0.z; As[nb][ak0+3][am0]=ra0.w;
            As[nb][ak1+0][am1]=ra1.x; As[nb][ak1+1][am1]=ra1.y; As[nb][ak1+2][am1]=ra1.z; As[nb][ak1+3][am1]=ra1.w;
            Bs[nb][ak0+0][am0]=rb0.x; Bs[nb][ak0+1][am0]=rb0.y; Bs[nb][ak0+2][am0]=rb0.z; Bs[nb][ak0+3][am0]=rb0.w;
            Bs[nb][ak1+0][am1]=rb1.x; Bs[nb][ak1+1][am1]=rb1.y; Bs[nb][ak1+2][am1]=rb1.z; Bs[nb][ak1+3][am1]=rb1.w;
        }
        __syncthreads();
    }

    // support-row norms (L2-hot recompute): thread pair per row
    {
        int n = tid>>1, half = tid&1;
        const float4* p = (const float4*)(Bp + (size_t)n*DD + half*512);
        float s = 0.f;
#pragma unroll 8
        for (int i=0;i<128;i++){ float4 v=p[i]; s += v.x*v.x + v.y*v.y + v.z*v.z + v.w*v.w; }
        s += __shfl_xor_sync(0xffffffffu, s, 1);
        if (!half) snorm[n] = s;
    }
    __syncthreads();

    // score = |s|^2 - 2*dot ; per-row chunk argmin with first-min tie-break
#pragma unroll
    for (int i=0;i<8;i++){
        float bv = 3.4e38f; int bi = 1<<30;
#pragma unroll
        for (int j=0;j<4;j++){
            float2 d = *(float2*)&acc[i][j];
            int n0 = (j<2) ? (tx*4 + j*2) : (64 + tx*4 + (j-2)*2);
            float s0 = snorm[n0]   - 2.f*d.x;
            float s1 = snorm[n0+1] - 2.f*d.y;
            if (s0 < bv || (s0==bv && n0   < bi)) { bv=s0; bi=n0;   }
            if (s1 < bv || (s1==bv && n0+1 < bi)) { bv=s1; bi=n0+1; }
        }
#pragma unroll
        for (int o=8;o;o>>=1){
            float ov = __shfl_down_sync(0xffffffffu, bv, o, 16);
            int   oi = __shfl_down_sync(0xffffffffu, bi, o, 16);
            if (ov < bv || (ov==bv && oi<bi)) { bv=ov; bi=oi; }
        }
        if (tx==0){
            int m = (i<4) ? (ty*4+i) : (64+ty*4+(i-4));
            g_cmin[((size_t)b*TT+m)*CHN + ch] = make_float2(bv, __int_as_float(ch*LLS + bi));
        }
    }
}

// ---------------- kernel 6: reduce chunk argmins ----------------
__global__ void k_nn(){
    int t = blockIdx.x*blockDim.x + threadIdx.x;
    if (t >= BB*TT) return;
    const float2* e = &g_cmin[(size_t)t*CHN];
    float2 v0 = e[0];
    float bv = v0.x; int bi = __float_as_int(v0.y);
#pragma unroll
    for (int c=1;c<CHN;c++){
        float2 v = e[c];
        if (v.x < bv){ bv=v.x; bi=__float_as_int(v.y); }
    }
    g_nn[t] = bi;
}

// ---------------- kernel 7: scores = tgt[nn] + 0.5*dot(test_mean, proto) ----------------
// grid (B, NT/8); warp w handles tag ng*8+w for every t.
__global__ __launch_bounds__(256) void k_final(const float* __restrict__ tgt,
                                               const float* __restrict__ proto,
                                               float* __restrict__ outs){
    __shared__ float sp[8*DD];   // 32 KB
    __shared__ float stm[DD];    // 4 KB
    int b = blockIdx.x, ng = blockIdx.y, tid = threadIdx.x;
    int w = tid>>5, lane = tid&31;
    const float* pb = proto + (size_t)b*NTAG*DD + (size_t)ng*8*DD;
    for (int i=tid;i<8*DD;i+=256) sp[i]=pb[i];
    __syncthreads();
    for (int t=0;t<TT;t++){
        const float* tm = g_test_mean + ((size_t)b*TT+t)*DD;
        for (int i=tid;i<DD;i+=256) stm[i]=tm[i];
        __syncthreads();
        float a = 0.f;
        const float* pr = sp + (size_t)w*DD;
#pragma unroll 8
        for (int i=lane;i<DD;i+=32) a += stm[i]*pr[i];
#pragma unroll
        for (int o=16;o;o>>=1) a += __shfl_xor_sync(0xffffffffu, a, o);
        if (lane==0){
            int n  = ng*8 + w;
            int nn = g_nn[b*TT+t];
            outs[((size_t)b*TT+t)*NTAG + n] =
                tgt[((size_t)b*SS+nn)*NTAG + n] + 0.5f*a;
        }
        __syncthreads();
    }
}

// ---------------- launch ----------------
extern "C" void kernel_launch(void* const* d_in, const int* in_sizes, int n_in,
                              void* d_out, int out_size){
    const float* test_reps = (const float*)d_in[0];
    const float* support   = (const float*)d_in[1];
    const float* tgt       = (const float*)d_in[4];
    float* out_scores = (float*)d_out;                                  // (B,T,NT)
    float* out_proto  = (float*)d_out + (size_t)BB*TT*NTAG;             // (B,NT,D)

    k_mean  <<<(BB*TT*DD/4 + 255)/256, 256>>>(test_reps);
    k_labels<<<(BB*SS + 255)/256, 256>>>(tgt);
    k_proto <<<dim3(BB, DD/256), 256>>>(support, out_proto);
    k_div   <<<dim3(BB, NTAG), 128>>>(out_proto);
    k_gemm  <<<dim3(CHN, BB), 256>>>(support);
    k_nn    <<<(BB*TT + 127)/128, 128>>>();
    k_final <<<dim3(BB, NTAG/8), 256>>>(tgt, out_proto, out_scores);
}

// round 2
// speedup vs baseline: 1.8648x; 1.8648x over previous
#include <cuda_runtime.h>
#include <cstdint>

#define BB 32
#define KKS 10
#define TT 128
#define LLS 128
#define DD 1024
#define NTAG 32
#define SS (KKS*LLS)     // 1280
#define CH 20            // chunks of 64 support rows
#define CROWS 64

typedef unsigned long long ull;

// ---------------- scratch (device globals; no allocation) ----------------
__device__ float  g_test_mean[BB*TT*DD];     // (B,T,D) 16 MB
__device__ int    g_list[BB*NTAG*256];       // per (b,tag) support-row index lists
__device__ int    g_cnt[BB*NTAG];
__device__ float2 g_cmin[BB*TT*CH];          // per-chunk (minval, idx-as-float)

// ---------------- kernel 1: test_mean = mean_k test_reps ----------------
__global__ void k_mean(const float* __restrict__ x){
    int idx = blockIdx.x*blockDim.x + threadIdx.x;
    const int n4 = BB*TT*DD/4;
    if (idx >= n4) return;
    int b   = idx / (TT*DD/4);
    int rem = idx - b*(TT*DD/4);
    const float4* p = (const float4*)x + (size_t)b*KKS*(TT*DD/4) + rem;
    float4 a = make_float4(0.f,0.f,0.f,0.f);
#pragma unroll
    for (int k=0;k<KKS;k++){
        float4 v = p[(size_t)k*(TT*DD/4)];
        a.x+=v.x; a.y+=v.y; a.z+=v.z; a.w+=v.w;
    }
    const float s = 1.0f/(float)KKS;
    a.x*=s; a.y*=s; a.z*=s; a.w*=s;
    ((float4*)g_test_mean)[idx] = a;
}

// ---------------- kernel 2: labels + deterministic per-tag index lists ----------------
__global__ __launch_bounds__(256) void k_labels(const float* __restrict__ tgt){
    __shared__ int lab[SS];
    int b = blockIdx.x, tid = threadIdx.x;
    for (int s = tid; s < SS; s += 256){
        const float* row = tgt + ((size_t)b*SS + s)*NTAG;
        float bv = row[0]; int bi = 0;
#pragma unroll
        for (int n=1;n<NTAG;n++){ float v=row[n]; if (v>bv){bv=v;bi=n;} }
        lab[s] = bi;
    }
    __syncthreads();
    if (tid < NTAG){
        int c = 0;
        int* lst = g_list + ((size_t)b*NTAG + tid)*256;
        for (int s=0;s<SS;s++) if (lab[s]==tid && c<256) lst[c++] = s;
        g_cnt[b*NTAG + tid] = c;
    }
}

// ---------------- kernel 3: prototypes = gather-sum / (count+1e-4) ----------------
// grid (B, NT); 256 threads; thread owns one float4 of D.
__global__ __launch_bounds__(256) void k_proto(const float* __restrict__ sup,
                                               float* __restrict__ proto){
    int b = blockIdx.x, n = blockIdx.y, tid = threadIdx.x;
    __shared__ int sl[256];
    int cnt = g_cnt[b*NTAG + n];
    const int* lst = g_list + ((size_t)b*NTAG + n)*256;
    if (tid < 256) sl[tid] = (tid < cnt) ? lst[tid] : 0;
    __syncthreads();
    float4 acc = make_float4(0.f,0.f,0.f,0.f);
    const float4* base = (const float4*)(sup + (size_t)b*SS*DD) + tid;
    for (int j=0;j<cnt;j++){
        float4 v = base[(size_t)sl[j]*(DD/4)];
        acc.x+=v.x; acc.y+=v.y; acc.z+=v.z; acc.w+=v.w;
    }
    float inv = 1.0f/((float)cnt + 1e-4f);
    acc.x*=inv; acc.y*=inv; acc.z*=inv; acc.w*=inv;
    ((float4*)(proto + ((size_t)b*NTAG + n)*DD))[tid] = acc;
}

// ---------------- kernel 4: fp32x2 SGEMM (128T x 64S x 1024) + chunk argmin ----------------
// grid (20 chunks, 32 batches); 256 threads; occupancy 2.
// thread (tx,ty): rows {ty*4..+3, 64+ty*4..+3}, cols {tx*4..+3}.
__global__ __launch_bounds__(256,2) void k_gemm(const float* __restrict__ sup){
    const int ch = blockIdx.x, b = blockIdx.y;
    const int tid = threadIdx.x;
    const int tx = tid & 15, ty = tid >> 4;
    __shared__ float As[2][16][128];     // 16 KB
    __shared__ float Bs[2][16][64];      //  8 KB
    __shared__ float snorm[CROWS];

    const float* A  = g_test_mean + (size_t)b*TT*DD;
    const float* Bp = sup + ((size_t)b*SS + (size_t)ch*CROWS)*DD;

    // A loader: 512 float4/tile -> 2 per thread. B loader: 256 float4 -> 1 per thread.
    const int ia0 = tid, ia1 = tid + 256;
    const int am0 = ia0>>2, ak0 = (ia0&3)*4;
    const int am1 = ia1>>2, ak1 = (ia1&3)*4;
    const int bm  = tid>>2, bk  = (tid&3)*4;
    const float* pA0 = A  + (size_t)am0*DD + ak0;
    const float* pA1 = A  + (size_t)am1*DD + ak1;
    const float* pB  = Bp + (size_t)bm *DD + bk;

    ull acc[8][2];
#pragma unroll
    for (int i=0;i<8;i++){ acc[i][0]=0ull; acc[i][1]=0ull; }
    float nrm = 0.f;

    float4 ra0 = *(const float4*)pA0;
    float4 ra1 = *(const float4*)pA1;
    float4 rb  = *(const float4*)pB;
    nrm += rb.x*rb.x + rb.y*rb.y + rb.z*rb.z + rb.w*rb.w;
    As[0][ak0+0][am0]=ra0.x; As[0][ak0+1][am0]=ra0.y; As[0][ak0+2][am0]=ra0.z; As[0][ak0+3][am0]=ra0.w;
    As[0][ak1+0][am1]=ra1.x; As[0][ak1+1][am1]=ra1.y; As[0][ak1+2][am1]=ra1.z; As[0][ak1+3][am1]=ra1.w;
    Bs[0][bk+0][bm]=rb.x;  Bs[0][bk+1][bm]=rb.y;  Bs[0][bk+2][bm]=rb.z;  Bs[0][bk+3][bm]=rb.w;
    __syncthreads();

    for (int kt=0; kt<DD/16; kt++){
        const int buf = kt & 1;
        if (kt < DD/16-1){
            const int off = (kt+1)*16;
            ra0 = *(const float4*)(pA0+off);
            ra1 = *(const float4*)(pA1+off);
            rb  = *(const float4*)(pB +off);
            nrm += rb.x*rb.x + rb.y*rb.y + rb.z*rb.z + rb.w*rb.w;
        }
#pragma unroll
        for (int kk=0;kk<16;kk++){
            float4 a0 = *(const float4*)&As[buf][kk][ty*4];
            float4 a1 = *(const float4*)&As[buf][kk][ty*4+64];
            const ull* br = (const ull*)&Bs[buf][kk][0];
            ull b0 = br[tx*2], b1 = br[tx*2+1];
            float av[8] = {a0.x,a0.y,a0.z,a0.w,a1.x,a1.y,a1.z,a1.w};
#pragma unroll
            for (int i=0;i<8;i++){
                ull aa;
                asm("mov.b64 %0, {%1, %1};" : "=l"(aa) : "f"(av[i]));
                asm("fma.rn.f32x2 %0, %1, %2, %0;" : "+l"(acc[i][0]) : "l"(aa), "l"(b0));
                asm("fma.rn.f32x2 %0, %1, %2, %0;" : "+l"(acc[i][1]) : "l"(aa), "l"(b1));
            }
        }
        if (kt < DD/16-1){
            const int nb = buf^1;
            As[nb][ak0+0][am0]=ra0.x; As[nb][ak0+1][am0]=ra0.y; As[nb][ak0+2][am0]=ra0.z; As[nb][ak0+3][am0]=ra0.w;
            As[nb][ak1+0][am1]=ra1.x; As[nb][ak1+1][am1]=ra1.y; As[nb][ak1+2][am1]=ra1.z; As[nb][ak1+3][am1]=ra1.w;
            Bs[nb][bk+0][bm]=rb.x;  Bs[nb][bk+1][bm]=rb.y;  Bs[nb][bk+2][bm]=rb.z;  Bs[nb][bk+3][bm]=rb.w;
        }
        __syncthreads();
    }

    // support-row norms: reduce 4 partials (lanes tid&3) per row, no extra global traffic
    nrm += __shfl_xor_sync(0xffffffffu, nrm, 2);
    nrm += __shfl_xor_sync(0xffffffffu, nrm, 1);
    if ((tid & 3) == 0) snorm[tid>>2] = nrm;
    __syncthreads();

    // score = |s|^2 - 2*dot ; per-row chunk argmin, first-min tie-break
#pragma unroll
    for (int i=0;i<8;i++){
        float bv = 3.4e38f; int bi = 1<<30;
#pragma unroll
        for (int j=0;j<2;j++){
            float2 d = *(float2*)&acc[i][j];
            int n0 = tx*4 + j*2;
            float s0 = snorm[n0]   - 2.f*d.x;
            float s1 = snorm[n0+1] - 2.f*d.y;
            if (s0 < bv || (s0==bv && n0   < bi)) { bv=s0; bi=n0;   }
            if (s1 < bv || (s1==bv && n0+1 < bi)) { bv=s1; bi=n0+1; }
        }
#pragma unroll
        for (int o=8;o;o>>=1){
            float ov = __shfl_down_sync(0xffffffffu, bv, o, 16);
            int   oi = __shfl_down_sync(0xffffffffu, bi, o, 16);
            if (ov < bv || (ov==bv && oi<bi)) { bv=ov; bi=oi; }
        }
        if (tx==0){
            int m = (i<4) ? (ty*4+i) : (64+ty*4+(i-4));
            g_cmin[((size_t)b*TT+m)*CH + ch] = make_float2(bv, __int_as_float(ch*CROWS + bi));
        }
    }
}

// ---------------- kernel 5: nn-reduce + scores GEMM fused ----------------
// grid (B, 2): 64 t-rows x 32 tags x K=1024 per block; 256 threads.
// thread: t-row = tid&63, tag group tg = tid>>6 (8 tags).
__global__ __launch_bounds__(256) void k_final(const float* __restrict__ tgt,
                                               const float* __restrict__ proto,
                                               float* __restrict__ outs){
    __shared__ float As[16][64];   // 4 KB  (k-major test rows)
    __shared__ float Bs[16][32];   // 2 KB  (k-major proto rows)
    __shared__ int   snn[64];
    int b = blockIdx.x, half = blockIdx.y, tid = threadIdx.x;
    const int trow = tid & 63, tg = tid >> 6;

    // fused nn reduction over 20 chunks (threads 0..63)
    if (tid < 64){
        const float2* e = &g_cmin[((size_t)b*TT + half*64 + tid)*CH];
        float2 v0 = e[0];
        float bv = v0.x; int bi = __float_as_int(v0.y);
#pragma unroll
        for (int c=1;c<CH;c++){
            float2 v = e[c];
            if (v.x < bv){ bv = v.x; bi = __float_as_int(v.y); }
        }
        snn[tid] = bi;
    }

    const float* Ab = g_test_mean + ((size_t)b*TT + half*64)*DD;
    const float* Pb = proto + (size_t)b*NTAG*DD;
    // loaders: As 256 float4 (all threads), Bs 128 float4 (threads<128)
    const int ar = tid>>2, ak = (tid&3)*4;

    ull acc[4];
#pragma unroll
    for (int i=0;i<4;i++) acc[i]=0ull;

    for (int kt=0; kt<DD/16; kt++){
        __syncthreads();
        {
            float4 va = *(const float4*)(Ab + (size_t)ar*DD + kt*16 + ak);
            As[ak+0][ar]=va.x; As[ak+1][ar]=va.y; As[ak+2][ar]=va.z; As[ak+3][ar]=va.w;
            if (tid < 128){
                float4 vb = *(const float4*)(Pb + (size_t)ar*DD + kt*16 + ak);
                Bs[ak+0][ar]=vb.x; Bs[ak+1][ar]=vb.y; Bs[ak+2][ar]=vb.z; Bs[ak+3][ar]=vb.w;
            }
        }
        __syncthreads();
#pragma unroll
        for (int kk=0;kk<16;kk++){
            float a = As[kk][trow];
            const ull* br = (const ull*)&Bs[kk][tg*8];
            ull aa;
            asm("mov.b64 %0, {%1, %1};" : "=l"(aa) : "f"(a));
#pragma unroll
            for (int i=0;i<4;i++)
                asm("fma.rn.f32x2 %0, %1, %2, %0;" : "+l"(acc[i]) : "l"(aa), "l"(br[i]));
        }
    }
    __syncthreads();

    int nn = snn[trow];
    const float4* tp = (const float4*)(tgt + ((size_t)b*SS + nn)*NTAG + tg*8);
    float4 t0 = tp[0], t1 = tp[1];
    float2 d0 = *(float2*)&acc[0], d1 = *(float2*)&acc[1];
    float2 d2 = *(float2*)&acc[2], d3 = *(float2*)&acc[3];
    float4 o0 = make_float4(t0.x+0.5f*d0.x, t0.y+0.5f*d0.y, t0.z+0.5f*d1.x, t0.w+0.5f*d1.y);
    float4 o1 = make_float4(t1.x+0.5f*d2.x, t1.y+0.5f*d2.y, t1.z+0.5f*d3.x, t1.w+0.5f*d3.y);
    float4* op = (float4*)(outs + ((size_t)b*TT + half*64 + trow)*NTAG + tg*8);
    op[0] = o0; op[1] = o1;
}

// ---------------- launch ----------------
extern "C" void kernel_launch(void* const* d_in, const int* in_sizes, int n_in,
                              void* d_out, int out_size){
    const float* test_reps = (const float*)d_in[0];
    const float* support   = (const float*)d_in[1];
    const float* tgt       = (const float*)d_in[4];
    float* out_scores = (float*)d_out;                                  // (B,T,NT)
    float* out_proto  = (float*)d_out + (size_t)BB*TT*NTAG;             // (B,NT,D)

    k_mean  <<<(BB*TT*DD/4 + 255)/256, 256>>>(test_reps);
    k_labels<<<BB, 256>>>(tgt);
    k_proto <<<dim3(BB, NTAG), 256>>>(support, out_proto);
    k_gemm  <<<dim3(CH, BB), 256>>>(support);
    k_final <<<dim3(BB, 2), 256>>>(tgt, out_proto, out_scores);
}